// round 14
// baseline (speedup 1.0000x reference)
#include <cuda_runtime.h>
#include <cuda_fp16.h>
#include <math.h>
#include <stdint.h>

// Problem constants
#define B_      8
#define SEQ_    16384
#define D_      384
#define H_      8
#define C_      48
#define TOK_    (B_ * SEQ_)          // 131072

// ---------------- scratch (static device globals; no allocs allowed) ----------------
__device__ __half g_eqh[(size_t)TOK_ * D_];          // 100 MB : exp(q) fp16
__device__ __half g_xh[(size_t)TOK_ * D_];           // 100 MB : x rounded to fp16
__device__ float  g_ctx[B_ * H_ * C_ * C_];          // unnormalized k^T v context
__device__ float  g_sum[B_ * H_ * C_];               // sum of exp(k) over tokens
__device__ __half g_ctxnTh[B_ * H_ * C_ * 56];       // normalized, transposed, fp16, padded
__device__ __half g_Wtqh[3 * D_ * D_];               // W_qkv^T, fp16  [1152][384]
__device__ __half g_Wtph[D_ * D_];                   // W_proj^T, fp16

__device__ __forceinline__ uint32_t smem_u32(const void* p) {
    uint32_t a;
    asm("{ .reg .u64 t; cvta.to.shared.u64 t, %1; cvt.u32.u64 %0, t; }" : "=r"(a) : "l"(p));
    return a;
}
__device__ __forceinline__ void cp_async16(uint32_t dst, const void* src) {
    asm volatile("cp.async.cg.shared.global [%0], [%1], 16;" :: "r"(dst), "l"(src));
}
__device__ __forceinline__ void mma_f16(float* c, const uint32_t* a, const uint32_t* b) {
    asm volatile(
        "mma.sync.aligned.m16n8k16.row.col.f32.f16.f16.f32 "
        "{%0,%1,%2,%3}, {%4,%5,%6,%7}, {%8,%9}, {%0,%1,%2,%3};"
        : "+f"(c[0]), "+f"(c[1]), "+f"(c[2]), "+f"(c[3])
        : "r"(a[0]), "r"(a[1]), "r"(a[2]), "r"(a[3]), "r"(b[0]), "r"(b[1]));
}
#define LDMX4(r0, r1, r2, r3, addr) \
    asm volatile("ldmatrix.sync.aligned.m8n8.x4.shared.b16 {%0,%1,%2,%3}, [%4];" \
        : "=r"(r0), "=r"(r1), "=r"(r2), "=r"(r3) : "r"(addr))
#define LDMX2(r0, r1, addr) \
    asm volatile("ldmatrix.sync.aligned.m8n8.x2.shared.b16 {%0,%1}, [%2];" \
        : "=r"(r0), "=r"(r1) : "r"(addr))

// ---------------- round x to fp16 (streaming) + zero accumulators ----------------
__global__ void round_f16_kernel(const float4* __restrict__ src, uint2* __restrict__ dst, int n4) {
    int i = blockIdx.x * 256 + threadIdx.x;
    if (i < B_ * H_ * C_ * C_) g_ctx[i] = 0.0f;
    if (i < B_ * H_ * C_)      g_sum[i] = 0.0f;
    if (i < n4) {
        float4 v = src[i];
        __half2 lo = __floats2half2_rn(v.x, v.y);
        __half2 hi = __floats2half2_rn(v.z, v.w);
        uint2 o;
        o.x = *(uint32_t*)&lo;
        o.y = *(uint32_t*)&hi;
        dst[i] = o;
    }
}

// ---------------- weight transpose + fp16 round: src[R][Ccols] -> dst[Ccols][R] ----------------
__global__ void transpose_f16_kernel(const float* __restrict__ src, __half* __restrict__ dst,
                                     int R, int Ccols) {
    __shared__ float t[32][33];
    int bx = blockIdx.x * 32, by = blockIdx.y * 32;
    int tx = threadIdx.x, ty = threadIdx.y;
#pragma unroll
    for (int j = 0; j < 32; j += 8)
        t[ty + j][tx] = src[(size_t)(by + ty + j) * Ccols + bx + tx];
    __syncthreads();
#pragma unroll
    for (int j = 0; j < 32; j += 8)
        dst[(size_t)(bx + ty + j) * R + by + tx] = __float2half_rn(t[tx][ty + j]);
}

#define BM_ 128
#define BK_ 32            // halves per chunk
#define PH_ 40            // halves per smem row slot

// ================= fused qkv-GEMM + ctx kernel — 512 threads, warp tile 32x72 =================
#define KVN_ 288
#define STH_ 136     // eT/vT row stride in halves (68 words)
#define KV_SMEM_BYTES ((2 * BM_ * PH_ + 2 * KVN_ * PH_) * 2)   // 66560

__global__ void __launch_bounds__(512, 1)
kv_ctx_kernel()
{
    extern __shared__ __half smemh[];
    __half* As = smemh;                          // [2][128][PH_]
    __half* Bs = smemh + 2 * BM_ * PH_;          // [2][288][PH_]
    __half* eT = smemh;                          // [96][STH_]  (epilogue view)
    __half* vT = smemh + 96 * STH_;              // [96][STH_]

    const int tid = threadIdx.x;
    const int wid = tid >> 5;        // 0..15
    const int lane = tid & 31;
    const int cg = blockIdx.x;
    const int ss = blockIdx.y;
    const int lr = lane >> 2;
    const int lc = lane & 3;
    const int wm = (wid & 3) * 32;   // 4 warps over M=128
    const int wn = (wid >> 2) * 72;  // 4 groups over N=288
    const int gr = tid >> 2;         // 0..127
    const int gc = (tid & 3) * 8;

    const uint32_t as_base = smem_u32(As);
    const uint32_t bs_base = smem_u32(Bs);

    const int lrow = lane & 7;
    const uint32_t a_lane = ((wm + lrow + ((lane >> 3) & 1) * 8) * PH_ + ((lane >> 4) & 1) * 8) * 2;
    const uint32_t b_lane = ((wn + lrow + ((lane >> 4) & 1) * 8) * PH_ + ((lane >> 3) & 1) * 8) * 2;

    const __half* Wq = g_Wtqh + (size_t)(cg * 96) * D_;
    const __half* Wk = g_Wtqh + (size_t)(D_ + cg * 96) * D_;
    const __half* Wv = g_Wtqh + (size_t)(2 * D_ + cg * 96) * D_;

    const int batch = ss / 32;

    float ctxa[3][4];
#pragma unroll
    for (int i = 0; i < 3; i++)
#pragma unroll
        for (int r = 0; r < 4; r++) ctxa[i][r] = 0.0f;
    float ssum = 0.0f;

    for (int rb = 0; rb < 4; rb++) {
        const size_t tok0 = ((size_t)ss * 4 + rb) * 128;
        const __half* A = g_xh + tok0 * D_;

        float acc[2][9][4];
#pragma unroll
        for (int i = 0; i < 2; i++)
#pragma unroll
            for (int j = 0; j < 9; j++)
#pragma unroll
                for (int r = 0; r < 4; r++) acc[i][j][r] = 0.0f;

        {
            cp_async16(as_base + (gr * PH_ + gc) * 2, &A[(size_t)gr * D_ + gc]);
#pragma unroll
            for (int i = 0; i < 3; i++) {
                int row = gr + i * 128;
                if (row < KVN_) {
                    const __half* src = (row < 96) ? &Wq[(size_t)row * D_ + gc]
                                     : (row < 192) ? &Wk[(size_t)(row - 96) * D_ + gc]
                                                   : &Wv[(size_t)(row - 192) * D_ + gc];
                    cp_async16(bs_base + (row * PH_ + gc) * 2, src);
                }
            }
            asm volatile("cp.async.commit_group;");
        }

#pragma unroll
        for (int c = 0; c < D_ / BK_; c++) {
            asm volatile("cp.async.wait_group 0;");
            __syncthreads();

            if (c + 1 < D_ / BK_) {
                const int k0 = (c + 1) * BK_;
                const int buf = (c + 1) & 1;
                const uint32_t ab = as_base + buf * BM_ * PH_ * 2;
                const uint32_t bb = bs_base + buf * KVN_ * PH_ * 2;
                cp_async16(ab + (gr * PH_ + gc) * 2, &A[(size_t)gr * D_ + k0 + gc]);
#pragma unroll
                for (int i = 0; i < 3; i++) {
                    int row = gr + i * 128;
                    if (row < KVN_) {
                        const __half* src = (row < 96) ? &Wq[(size_t)row * D_ + k0 + gc]
                                         : (row < 192) ? &Wk[(size_t)(row - 96) * D_ + k0 + gc]
                                                       : &Wv[(size_t)(row - 192) * D_ + k0 + gc];
                        cp_async16(bb + (row * PH_ + gc) * 2, src);
                    }
                }
                asm volatile("cp.async.commit_group;");
            }

            const uint32_t abuf = as_base + (c & 1) * BM_ * PH_ * 2 + a_lane;
            const uint32_t bbuf = bs_base + (c & 1) * KVN_ * PH_ * 2 + b_lane;

#pragma unroll
            for (int ks = 0; ks < 2; ks++) {
                uint32_t afr[2][4];
#pragma unroll
                for (int mi = 0; mi < 2; mi++)
                    LDMX4(afr[mi][0], afr[mi][1], afr[mi][2], afr[mi][3],
                          abuf + mi * 16 * PH_ * 2 + ks * 32);
                uint32_t bfr[9][2];
#pragma unroll
                for (int p = 0; p < 4; p++) {
                    uint32_t t0, t1, t2, t3;
                    LDMX4(t0, t1, t2, t3, bbuf + p * 16 * PH_ * 2 + ks * 32);
                    bfr[2 * p][0] = t0; bfr[2 * p][1] = t1;
                    bfr[2 * p + 1][0] = t2; bfr[2 * p + 1][1] = t3;
                }
                LDMX2(bfr[8][0], bfr[8][1], bbuf + 4 * 16 * PH_ * 2 + ks * 32);
#pragma unroll
                for (int mi = 0; mi < 2; mi++)
#pragma unroll
                    for (int nj = 0; nj < 9; nj++)
                        mma_f16(acc[mi][nj], afr[mi], bfr[nj]);
            }
            __syncthreads();
        }

        // ---- epilogue: q -> exp -> gmem fp16 ; k -> exp -> eT ; v -> vT ----
        {
            __half* eqb = g_eqh + tok0 * D_ + cg * 96;
#pragma unroll
            for (int nj = 0; nj < 9; nj++) {
                const int chbase = wn + nj * 8;
                if (chbase < 96) {
                    const int ch = chbase + lc * 2;
#pragma unroll
                    for (int mi = 0; mi < 2; mi++) {
                        int tl = wm + mi * 16 + lr;
                        __half2 v0 = __floats2half2_rn(__expf(acc[mi][nj][0]), __expf(acc[mi][nj][1]));
                        __half2 v1 = __floats2half2_rn(__expf(acc[mi][nj][2]), __expf(acc[mi][nj][3]));
                        *(__half2*)&eqb[(size_t)tl * D_ + ch] = v0;
                        *(__half2*)&eqb[(size_t)(tl + 8) * D_ + ch] = v1;
                    }
                } else if (chbase < 192) {
#pragma unroll
                    for (int mi = 0; mi < 2; mi++) {
#pragma unroll
                        for (int r = 0; r < 4; r++) {
                            int ch = chbase - 96 + lc * 2 + (r & 1);
                            int tl = wm + mi * 16 + lr + ((r >> 1) ? 8 : 0);
                            eT[ch * STH_ + tl] = __float2half_rn(__expf(acc[mi][nj][r]));
                        }
                    }
                } else {
#pragma unroll
                    for (int mi = 0; mi < 2; mi++) {
#pragma unroll
                        for (int r = 0; r < 4; r++) {
                            int ch = chbase - 192 + lc * 2 + (r & 1);
                            int tl = wm + mi * 16 + lr + ((r >> 1) ? 8 : 0);
                            vT[ch * STH_ + tl] = __float2half_rn(acc[mi][nj][r]);
                        }
                    }
                }
            }
        }
        __syncthreads();

        // ---- ctx += e^T v via fp16 MMA: 36 m16n8 tiles over 16 warps ----
        const uint32_t* eTw = (const uint32_t*)eT;
        const uint32_t* vTw = (const uint32_t*)vT;
#pragma unroll
        for (int i = 0; i < 3; i++) {
            int t = wid + 16 * i;
            if (t < 36) {
                int head = t / 18, rem = t % 18;
                int mi = rem / 6, nj = rem % 6;
                const int ar = head * 48 + mi * 16;
                const int br = head * 48 + nj * 8;
#pragma unroll
                for (int ks = 0; ks < 8; ks++) {
                    const int kw = ks * 8 + lc;
                    uint32_t a[4], b[2];
                    a[0] = eTw[(ar + lr) * 68 + kw];
                    a[1] = eTw[(ar + lr + 8) * 68 + kw];
                    a[2] = eTw[(ar + lr) * 68 + kw + 4];
                    a[3] = eTw[(ar + lr + 8) * 68 + kw + 4];
                    b[0] = vTw[(br + lr) * 68 + kw];
                    b[1] = vTw[(br + lr) * 68 + kw + 4];
                    mma_f16(ctxa[i], a, b);
                }
            }
        }

        // ---- per-channel exp-sum ----
        if (tid < 96) {
            const uint32_t* row = (const uint32_t*)(eT + tid * STH_);
            float s = 0.0f;
#pragma unroll
            for (int j = 0; j < 64; j++) {
                uint32_t w = row[j];
                float2 f = __half22float2(*(const __half2*)&w);
                s += f.x + f.y;
            }
            ssum += s;
        }
        __syncthreads();
    }

    // ---- atomics ----
#pragma unroll
    for (int i = 0; i < 3; i++) {
        int t = wid + 16 * i;
        if (t < 36) {
            int head = t / 18, rem = t % 18;
            int mi = rem / 6, nj = rem % 6;
            int bh = (batch * H_ + cg * 2 + head);
#pragma unroll
            for (int r = 0; r < 4; r++) {
                int c = mi * 16 + lr + ((r >> 1) ? 8 : 0);
                int d = nj * 8 + lc * 2 + (r & 1);
                atomicAdd(&g_ctx[((size_t)bh * C_ + c) * C_ + d], ctxa[i][r]);
            }
        }
    }
    if (tid < 96) {
        int head = tid / 48;
        atomicAdd(&g_sum[(batch * H_ + cg * 2 + head) * C_ + tid % 48], ssum);
    }
}

// ================= global context normalization (one-shot, fp16 out) =================
#define ACT_STH 56
__global__ void ctxn_norm_kernel()
{
    __shared__ float sinv[C_];
    const int bh = blockIdx.x;
    if (threadIdx.x < C_) sinv[threadIdx.x] = 1.0f / g_sum[bh * C_ + threadIdx.x];
    __syncthreads();
    const float* cb = g_ctx + (size_t)bh * (C_ * C_);
    __half* ob = g_ctxnTh + (size_t)bh * (C_ * ACT_STH);
    for (int i = threadIdx.x; i < C_ * C_; i += 256) {
        int c = i / C_, d = i % C_;
        ob[d * ACT_STH + c] = __float2half_rn(cb[i] * sinv[c]);
    }
}

// ================= fused attn + proj: 512 threads, CTA = 64 tokens x N=384 =================
#define AQ_ST 392                            // eq row stride in halves (196 words)
#define AP_EQ_B    (64 * AQ_ST * 2)          // 50176
#define AP_CTX_B   (H_ * C_ * ACT_STH * 2)   // 43008
#define AP_W_B     (2 * D_ * PH_ * 2)        // 61440
#define AP_SMEM_BYTES (AP_EQ_B + AP_CTX_B + AP_W_B + 2048)

__global__ void __launch_bounds__(512, 1)
attn_proj_kernel(const float* __restrict__ bias, float* __restrict__ out)
{
    extern __shared__ char smem[];
    __half* eqA  = (__half*)smem;                       // [64][AQ_ST]
    __half* ctxs = (__half*)(smem + AP_EQ_B);           // [8*48][ACT_STH]
    __half* wbuf = (__half*)(smem + AP_EQ_B + AP_CTX_B);// [2][384][PH_]
    float*  srow = (float*)(smem + AP_EQ_B + AP_CTX_B + AP_W_B);  // [64][8]

    const int tid = threadIdx.x;
    const int wid = tid >> 5;        // 0..15
    const int lane = tid & 31;
    const int lr = lane >> 2;
    const int lc = lane & 3;
    const size_t tok0 = (size_t)blockIdx.x * 64;
    const int batch = blockIdx.x / (SEQ_ / 64);

    const uint32_t eq_base = smem_u32(eqA);
    const uint32_t ctx_base = smem_u32(ctxs);
    const uint32_t w_base = smem_u32(wbuf);

    // ---- group 1: eq tile + ctxT ----
    {
        const __half* eqg = g_eqh + tok0 * D_;
        const int r8 = tid >> 3;            // 0..63
        const int c8 = (tid & 7) * 8;
#pragma unroll
        for (int i = 0; i < 6; i++) {
            int col = c8 + i * 64;
            cp_async16(eq_base + (r8 * AQ_ST + col) * 2, &eqg[(size_t)r8 * D_ + col]);
        }
        const __half* cg = g_ctxnTh + (size_t)batch * (H_ * C_ * ACT_STH);
        for (int i = tid; i < H_ * C_ * (ACT_STH / 8); i += 512) {
            int r = i / 7, u = i % 7;
            cp_async16(ctx_base + (r * ACT_STH + u * 8) * 2, &cg[(size_t)r * ACT_STH + u * 8]);
        }
        asm volatile("cp.async.commit_group;");
    }
    // ---- group 2: W chunk 0 ----
    const int gr = tid >> 2;        // 0..127
    const int gc = (tid & 3) * 8;
    {
#pragma unroll
        for (int i = 0; i < 3; i++) {
            int row = gr + i * 128;
            cp_async16(w_base + (row * PH_ + gc) * 2, &g_Wtph[(size_t)row * D_ + gc]);
        }
        asm volatile("cp.async.commit_group;");
    }
    asm volatile("cp.async.wait_group 1;");
    __syncthreads();

    // ---- rowsums: 512 (token, head) pairs, one per thread ----
    {
        int r = tid >> 3, h = tid & 7;
        const uint32_t* rp = (const uint32_t*)(eqA + r * AQ_ST + h * C_);
        float s = 0.0f;
#pragma unroll
        for (int j = 0; j < 24; j++) {
            uint32_t w = rp[j];
            float2 f = __half22float2(*(const __half2*)&w);
            s += f.x + f.y;
        }
        srow[r * 8 + h] = 1.0f / s;
    }
    __syncthreads();

    // ---- attn: 2 warps per head; warp handles rows msub..msub+31 of head h ----
    {
        const int h = wid >> 1;
        const int msub = (wid & 1) * 32;
        const uint32_t* eqw = (const uint32_t*)eqA;
        const uint32_t* cw = (const uint32_t*)ctxs;
        float acc[2][6][4];
#pragma unroll
        for (int i = 0; i < 2; i++)
#pragma unroll
            for (int j = 0; j < 6; j++)
#pragma unroll
                for (int r = 0; r < 4; r++) acc[i][j][r] = 0.0f;

#pragma unroll
        for (int ks = 0; ks < 3; ks++) {
            const int kw = ks * 8 + lc;
            uint32_t afr[2][4];
#pragma unroll
            for (int mi = 0; mi < 2; mi++) {
                int r = msub + mi * 16 + lr;
                afr[mi][0] = eqw[r * (AQ_ST / 2) + h * 24 + kw];
                afr[mi][1] = eqw[(r + 8) * (AQ_ST / 2) + h * 24 + kw];
                afr[mi][2] = eqw[r * (AQ_ST / 2) + h * 24 + kw + 4];
                afr[mi][3] = eqw[(r + 8) * (AQ_ST / 2) + h * 24 + kw + 4];
            }
            uint32_t bfr[6][2];
#pragma unroll
            for (int nj = 0; nj < 6; nj++) {
                int nn = h * C_ + nj * 8 + lr;
                bfr[nj][0] = cw[nn * (ACT_STH / 2) + kw];
                bfr[nj][1] = cw[nn * (ACT_STH / 2) + kw + 4];
            }
#pragma unroll
            for (int mi = 0; mi < 2; mi++)
#pragma unroll
                for (int nj = 0; nj < 6; nj++)
                    mma_f16(acc[mi][nj], afr[mi], bfr[nj]);
        }
        __syncwarp();
#pragma unroll
        for (int mi = 0; mi < 2; mi++) {
            const int ra = msub + mi * 16 + lr;
            const float sa = srow[ra * 8 + h];
            const float sb = srow[(ra + 8) * 8 + h];
#pragma unroll
            for (int nj = 0; nj < 6; nj++) {
                const int col = h * C_ + nj * 8 + lc * 2;
                __half2 v0 = __floats2half2_rn(acc[mi][nj][0] * sa, acc[mi][nj][1] * sa);
                __half2 v1 = __floats2half2_rn(acc[mi][nj][2] * sb, acc[mi][nj][3] * sb);
                *(__half2*)&eqA[ra * AQ_ST + col] = v0;
                *(__half2*)&eqA[(ra + 8) * AQ_ST + col] = v1;
            }
        }
    }
    __syncthreads();

    // ---- proj mainloop: warp tile 32x48 (16 warps over 64x384) ----
    const int wm = (wid & 1) * 32;
    const int wn = (wid >> 1) * 48;
    const int lrow = lane & 7;
    const uint32_t a_lane = eq_base + ((wm + lrow + ((lane >> 3) & 1) * 8) * AQ_ST + ((lane >> 4) & 1) * 8) * 2;
    const uint32_t b_lane = ((wn + lrow + ((lane >> 4) & 1) * 8) * PH_ + ((lane >> 3) & 1) * 8) * 2;

    float acc[2][6][4];
#pragma unroll
    for (int i = 0; i < 2; i++)
#pragma unroll
        for (int j = 0; j < 6; j++)
#pragma unroll
            for (int r = 0; r < 4; r++) acc[i][j][r] = 0.0f;

#pragma unroll
    for (int c = 0; c < 12; c++) {
        asm volatile("cp.async.wait_group 0;");
        __syncthreads();

        if (c + 1 < 12) {
            const int k0 = (c + 1) * BK_;
            const uint32_t bb = w_base + ((c + 1) & 1) * D_ * PH_ * 2;
#pragma unroll
            for (int i = 0; i < 3; i++) {
                int row = gr + i * 128;
                cp_async16(bb + (row * PH_ + gc) * 2, &g_Wtph[(size_t)row * D_ + k0 + gc]);
            }
            asm volatile("cp.async.commit_group;");
        }

        const uint32_t abuf = a_lane + c * 64;   // chunk c -> +64 bytes (32 halves)
        const uint32_t bbuf = w_base + (c & 1) * D_ * PH_ * 2 + b_lane;

#pragma unroll
        for (int ks = 0; ks < 2; ks++) {
            uint32_t afr[2][4];
#pragma unroll
            for (int mi = 0; mi < 2; mi++)
                LDMX4(afr[mi][0], afr[mi][1], afr[mi][2], afr[mi][3],
                      abuf + mi * 16 * AQ_ST * 2 + ks * 32);
            uint32_t bfr[6][2];
#pragma unroll
            for (int p = 0; p < 3; p++) {
                uint32_t t0, t1, t2, t3;
                LDMX4(t0, t1, t2, t3, bbuf + p * 16 * PH_ * 2 + ks * 32);
                bfr[2 * p][0] = t0; bfr[2 * p][1] = t1;
                bfr[2 * p + 1][0] = t2; bfr[2 * p + 1][1] = t3;
            }
#pragma unroll
            for (int mi = 0; mi < 2; mi++)
#pragma unroll
                for (int nj = 0; nj < 6; nj++)
                    mma_f16(acc[mi][nj], afr[mi], bfr[nj]);
        }
        __syncthreads();
    }

    // ---- epilogue: fp32 out + bias ----
#pragma unroll
    for (int mi = 0; mi < 2; mi++) {
        const size_t r0 = tok0 + wm + mi * 16 + lr;
#pragma unroll
        for (int nj = 0; nj < 6; nj++) {
            const int col = wn + nj * 8 + lc * 2;
            float2 b2 = *(const float2*)&bias[col];
            float2 v0 = make_float2(acc[mi][nj][0] + b2.x, acc[mi][nj][1] + b2.y);
            float2 v1 = make_float2(acc[mi][nj][2] + b2.x, acc[mi][nj][3] + b2.y);
            *(float2*)&out[r0 * D_ + col] = v0;
            *(float2*)&out[(r0 + 8) * D_ + col] = v1;
        }
    }
}

// ---------------- launch ----------------
extern "C" void kernel_launch(void* const* d_in, const int* in_sizes, int n_in,
                              void* d_out, int out_size)
{
    const float* x     = (const float*)d_in[0];
    const float* Wqkv  = (const float*)d_in[1];
    const float* Wproj = (const float*)d_in[2];
    const float* bproj = (const float*)d_in[3];
    float* out = (float*)d_out;

    __half *p_xh, *p_wtqh, *p_wtph;
    cudaGetSymbolAddress((void**)&p_xh, g_xh);
    cudaGetSymbolAddress((void**)&p_wtqh, g_Wtqh);
    cudaGetSymbolAddress((void**)&p_wtph, g_Wtph);

    cudaFuncSetAttribute(kv_ctx_kernel, cudaFuncAttributeMaxDynamicSharedMemorySize, KV_SMEM_BYTES);
    cudaFuncSetAttribute(attn_proj_kernel, cudaFuncAttributeMaxDynamicSharedMemorySize, AP_SMEM_BYTES);

    // 0) prepass: round x to fp16 (+ zero accumulators); transpose weights
    {
        int n4 = TOK_ * D_ / 4;
        round_f16_kernel<<<(n4 + 255) / 256, 256>>>((const float4*)x, (uint2*)p_xh, n4);
    }
    transpose_f16_kernel<<<dim3(3 * D_ / 32, D_ / 32), dim3(32, 8)>>>(Wqkv, p_wtqh, D_, 3 * D_);
    transpose_f16_kernel<<<dim3(D_ / 32, D_ / 32), dim3(32, 8)>>>(Wproj, p_wtph, D_, D_);

    // 1) fused qkv-GEMM + exp + context accumulation (writes g_eqh, g_ctx, g_sum)
    {
        dim3 grid(4, 256);
        kv_ctx_kernel<<<grid, 512, KV_SMEM_BYTES>>>();
    }

    // 2) one-shot context normalization
    ctxn_norm_kernel<<<B_ * H_, 256>>>();

    // 3) fused attn + proj (reads g_eqh + g_ctxnTh, writes out)
    attn_proj_kernel<<<TOK_ / 64, 512, AP_SMEM_BYTES>>>(bproj, out);
}

// round 15
// speedup vs baseline: 1.0011x; 1.0011x over previous
#include <cuda_runtime.h>
#include <cuda_fp16.h>
#include <math.h>
#include <stdint.h>

// Problem constants
#define B_      8
#define SEQ_    16384
#define D_      384
#define H_      8
#define C_      48
#define TOK_    (B_ * SEQ_)          // 131072

// ---------------- scratch (static device globals; no allocs allowed) ----------------
__device__ __half g_eqh[(size_t)TOK_ * D_];          // 100 MB : exp(q) fp16
__device__ __half g_xh[(size_t)TOK_ * D_];           // 100 MB : x rounded to fp16
__device__ float  g_ctx[B_ * H_ * C_ * C_];          // unnormalized k^T v context
__device__ float  g_sum[B_ * H_ * C_];               // sum of exp(k) over tokens
__device__ __half g_Mh[(size_t)B_ * D_ * D_];        // fused ctxn@Wproj, [b][n][hc] fp16
__device__ __half g_Wtqh[3 * D_ * D_];               // W_qkv^T, fp16  [1152][384]

__device__ __forceinline__ uint32_t smem_u32(const void* p) {
    uint32_t a;
    asm("{ .reg .u64 t; cvta.to.shared.u64 t, %1; cvt.u32.u64 %0, t; }" : "=r"(a) : "l"(p));
    return a;
}
__device__ __forceinline__ void cp_async16(uint32_t dst, const void* src) {
    asm volatile("cp.async.cg.shared.global [%0], [%1], 16;" :: "r"(dst), "l"(src));
}
__device__ __forceinline__ void mma_f16(float* c, const uint32_t* a, const uint32_t* b) {
    asm volatile(
        "mma.sync.aligned.m16n8k16.row.col.f32.f16.f16.f32 "
        "{%0,%1,%2,%3}, {%4,%5,%6,%7}, {%8,%9}, {%0,%1,%2,%3};"
        : "+f"(c[0]), "+f"(c[1]), "+f"(c[2]), "+f"(c[3])
        : "r"(a[0]), "r"(a[1]), "r"(a[2]), "r"(a[3]), "r"(b[0]), "r"(b[1]));
}
#define LDMX4(r0, r1, r2, r3, addr) \
    asm volatile("ldmatrix.sync.aligned.m8n8.x4.shared.b16 {%0,%1,%2,%3}, [%4];" \
        : "=r"(r0), "=r"(r1), "=r"(r2), "=r"(r3) : "r"(addr))
#define LDMX2(r0, r1, addr) \
    asm volatile("ldmatrix.sync.aligned.m8n8.x2.shared.b16 {%0,%1}, [%2];" \
        : "=r"(r0), "=r"(r1) : "r"(addr))

// ---------------- round x to fp16 (streaming) + zero accumulators ----------------
__global__ void round_f16_kernel(const float4* __restrict__ src, uint2* __restrict__ dst, int n4) {
    int i = blockIdx.x * 256 + threadIdx.x;
    if (i < B_ * H_ * C_ * C_) g_ctx[i] = 0.0f;
    if (i < B_ * H_ * C_)      g_sum[i] = 0.0f;
    if (i < n4) {
        float4 v = src[i];
        __half2 lo = __floats2half2_rn(v.x, v.y);
        __half2 hi = __floats2half2_rn(v.z, v.w);
        uint2 o;
        o.x = *(uint32_t*)&lo;
        o.y = *(uint32_t*)&hi;
        dst[i] = o;
    }
}

// ---------------- weight transpose + fp16 round: src[R][Ccols] -> dst[Ccols][R] ----------------
__global__ void transpose_f16_kernel(const float* __restrict__ src, __half* __restrict__ dst,
                                     int R, int Ccols) {
    __shared__ float t[32][33];
    int bx = blockIdx.x * 32, by = blockIdx.y * 32;
    int tx = threadIdx.x, ty = threadIdx.y;
#pragma unroll
    for (int j = 0; j < 32; j += 8)
        t[ty + j][tx] = src[(size_t)(by + ty + j) * Ccols + bx + tx];
    __syncthreads();
#pragma unroll
    for (int j = 0; j < 32; j += 8)
        dst[(size_t)(bx + ty + j) * R + by + tx] = __float2half_rn(t[tx][ty + j]);
}

#define BM_ 128
#define BK_ 32            // halves per chunk
#define PH_ 40            // halves per smem row slot

// ================= fused qkv-GEMM + ctx kernel (R13 proven config: 256 thr) =================
#define KVN_ 288
#define STH_ 136     // eT/vT row stride in halves (68 words)
#define KV_SMEM_BYTES ((2 * BM_ * PH_ + 2 * KVN_ * PH_) * 2)   // 66560

__global__ void __launch_bounds__(256, 1)
kv_ctx_kernel()
{
    extern __shared__ __half smemh[];
    __half* As = smemh;                          // [2][128][PH_]
    __half* Bs = smemh + 2 * BM_ * PH_;          // [2][288][PH_]
    __half* eT = smemh;                          // [96][STH_]  (epilogue view)
    __half* vT = smemh + 96 * STH_;              // [96][STH_]

    const int tid = threadIdx.x;
    const int wid = tid >> 5;
    const int lane = tid & 31;
    const int cg = blockIdx.x;
    const int ss = blockIdx.y;
    const int lr = lane >> 2;
    const int lc = lane & 3;
    const int wm = (wid & 1) * 64;
    const int wn = (wid >> 1) * 72;   // 4 warps over N=288
    const int gr = tid >> 2;          // 0..63
    const int gc = (tid & 3) * 8;

    const uint32_t as_base = smem_u32(As);
    const uint32_t bs_base = smem_u32(Bs);

    const int lrow = lane & 7;
    const uint32_t a_lane = ((wm + lrow + ((lane >> 3) & 1) * 8) * PH_ + ((lane >> 4) & 1) * 8) * 2;
    const uint32_t b_lane = ((wn + lrow + ((lane >> 4) & 1) * 8) * PH_ + ((lane >> 3) & 1) * 8) * 2;

    const __half* Wq = g_Wtqh + (size_t)(cg * 96) * D_;
    const __half* Wk = g_Wtqh + (size_t)(D_ + cg * 96) * D_;
    const __half* Wv = g_Wtqh + (size_t)(2 * D_ + cg * 96) * D_;

    const int batch = ss / 32;

    float ctxa[5][4];
#pragma unroll
    for (int i = 0; i < 5; i++)
#pragma unroll
        for (int r = 0; r < 4; r++) ctxa[i][r] = 0.0f;
    float ssum = 0.0f;

    for (int rb = 0; rb < 4; rb++) {
        const size_t tok0 = ((size_t)ss * 4 + rb) * 128;
        const __half* A = g_xh + tok0 * D_;

        float acc[4][9][4];
#pragma unroll
        for (int i = 0; i < 4; i++)
#pragma unroll
            for (int j = 0; j < 9; j++)
#pragma unroll
                for (int r = 0; r < 4; r++) acc[i][j][r] = 0.0f;

        {
#pragma unroll
            for (int i = 0; i < 2; i++) {
                int row = gr + i * 64;
                cp_async16(as_base + (row * PH_ + gc) * 2, &A[(size_t)row * D_ + gc]);
            }
#pragma unroll
            for (int i = 0; i < 5; i++) {
                int row = gr + i * 64;
                if (row < KVN_) {
                    const __half* src = (row < 96) ? &Wq[(size_t)row * D_ + gc]
                                     : (row < 192) ? &Wk[(size_t)(row - 96) * D_ + gc]
                                                   : &Wv[(size_t)(row - 192) * D_ + gc];
                    cp_async16(bs_base + (row * PH_ + gc) * 2, src);
                }
            }
            asm volatile("cp.async.commit_group;");
        }

#pragma unroll
        for (int c = 0; c < D_ / BK_; c++) {
            asm volatile("cp.async.wait_group 0;");
            __syncthreads();

            if (c + 1 < D_ / BK_) {
                const int k0 = (c + 1) * BK_;
                const int buf = (c + 1) & 1;
                const uint32_t ab = as_base + buf * BM_ * PH_ * 2;
                const uint32_t bb = bs_base + buf * KVN_ * PH_ * 2;
#pragma unroll
                for (int i = 0; i < 2; i++) {
                    int row = gr + i * 64;
                    cp_async16(ab + (row * PH_ + gc) * 2, &A[(size_t)row * D_ + k0 + gc]);
                }
#pragma unroll
                for (int i = 0; i < 5; i++) {
                    int row = gr + i * 64;
                    if (row < KVN_) {
                        const __half* src = (row < 96) ? &Wq[(size_t)row * D_ + k0 + gc]
                                         : (row < 192) ? &Wk[(size_t)(row - 96) * D_ + k0 + gc]
                                                       : &Wv[(size_t)(row - 192) * D_ + k0 + gc];
                        cp_async16(bb + (row * PH_ + gc) * 2, src);
                    }
                }
                asm volatile("cp.async.commit_group;");
            }

            const uint32_t abuf = as_base + (c & 1) * BM_ * PH_ * 2 + a_lane;
            const uint32_t bbuf = bs_base + (c & 1) * KVN_ * PH_ * 2 + b_lane;

#pragma unroll
            for (int ks = 0; ks < 2; ks++) {
                uint32_t afr[4][4];
#pragma unroll
                for (int mi = 0; mi < 4; mi++)
                    LDMX4(afr[mi][0], afr[mi][1], afr[mi][2], afr[mi][3],
                          abuf + mi * 16 * PH_ * 2 + ks * 32);
                uint32_t bfr[9][2];
#pragma unroll
                for (int p = 0; p < 4; p++) {
                    uint32_t t0, t1, t2, t3;
                    LDMX4(t0, t1, t2, t3, bbuf + p * 16 * PH_ * 2 + ks * 32);
                    bfr[2 * p][0] = t0; bfr[2 * p][1] = t1;
                    bfr[2 * p + 1][0] = t2; bfr[2 * p + 1][1] = t3;
                }
                LDMX2(bfr[8][0], bfr[8][1], bbuf + 4 * 16 * PH_ * 2 + ks * 32);
#pragma unroll
                for (int mi = 0; mi < 4; mi++)
#pragma unroll
                    for (int nj = 0; nj < 9; nj++)
                        mma_f16(acc[mi][nj], afr[mi], bfr[nj]);
            }
            __syncthreads();
        }

        // ---- epilogue: q -> exp -> gmem fp16 ; k -> exp -> eT ; v -> vT ----
        {
            __half* eqb = g_eqh + tok0 * D_ + cg * 96;
#pragma unroll
            for (int nj = 0; nj < 9; nj++) {
                const int chbase = wn + nj * 8;
                if (chbase < 96) {
                    const int ch = chbase + lc * 2;
#pragma unroll
                    for (int mi = 0; mi < 4; mi++) {
                        int tl = wm + mi * 16 + lr;
                        __half2 v0 = __floats2half2_rn(__expf(acc[mi][nj][0]), __expf(acc[mi][nj][1]));
                        __half2 v1 = __floats2half2_rn(__expf(acc[mi][nj][2]), __expf(acc[mi][nj][3]));
                        *(__half2*)&eqb[(size_t)tl * D_ + ch] = v0;
                        *(__half2*)&eqb[(size_t)(tl + 8) * D_ + ch] = v1;
                    }
                } else if (chbase < 192) {
#pragma unroll
                    for (int mi = 0; mi < 4; mi++) {
#pragma unroll
                        for (int r = 0; r < 4; r++) {
                            int ch = chbase - 96 + lc * 2 + (r & 1);
                            int tl = wm + mi * 16 + lr + ((r >> 1) ? 8 : 0);
                            eT[ch * STH_ + tl] = __float2half_rn(__expf(acc[mi][nj][r]));
                        }
                    }
                } else {
#pragma unroll
                    for (int mi = 0; mi < 4; mi++) {
#pragma unroll
                        for (int r = 0; r < 4; r++) {
                            int ch = chbase - 192 + lc * 2 + (r & 1);
                            int tl = wm + mi * 16 + lr + ((r >> 1) ? 8 : 0);
                            vT[ch * STH_ + tl] = __float2half_rn(acc[mi][nj][r]);
                        }
                    }
                }
            }
        }
        __syncthreads();

        // ---- ctx += e^T v via fp16 MMA: 36 m16n8 tiles, k=128 (8 k16-steps) ----
        const uint32_t* eTw = (const uint32_t*)eT;
        const uint32_t* vTw = (const uint32_t*)vT;
#pragma unroll
        for (int i = 0; i < 5; i++) {
            int t = wid + 8 * i;
            if (t < 36) {
                int head = t / 18, rem = t % 18;
                int mi = rem / 6, nj = rem % 6;
                const int ar = head * 48 + mi * 16;
                const int br = head * 48 + nj * 8;
#pragma unroll
                for (int ks = 0; ks < 8; ks++) {
                    const int kw = ks * 8 + lc;
                    uint32_t a[4], b[2];
                    a[0] = eTw[(ar + lr) * 68 + kw];
                    a[1] = eTw[(ar + lr + 8) * 68 + kw];
                    a[2] = eTw[(ar + lr) * 68 + kw + 4];
                    a[3] = eTw[(ar + lr + 8) * 68 + kw + 4];
                    b[0] = vTw[(br + lr) * 68 + kw];
                    b[1] = vTw[(br + lr) * 68 + kw + 4];
                    mma_f16(ctxa[i], a, b);
                }
            }
        }

        // ---- per-channel exp-sum ----
        if (tid < 96) {
            const uint32_t* row = (const uint32_t*)(eT + tid * STH_);
            float s = 0.0f;
#pragma unroll
            for (int j = 0; j < 64; j++) {
                uint32_t w = row[j];
                float2 f = __half22float2(*(const __half2*)&w);
                s += f.x + f.y;
            }
            ssum += s;
        }
        __syncthreads();
    }

    // ---- atomics ----
#pragma unroll
    for (int i = 0; i < 5; i++) {
        int t = wid + 8 * i;
        if (t < 36) {
            int head = t / 18, rem = t % 18;
            int mi = rem / 6, nj = rem % 6;
            int bh = (batch * H_ + cg * 2 + head);
#pragma unroll
            for (int r = 0; r < 4; r++) {
                int c = mi * 16 + lr + ((r >> 1) ? 8 : 0);
                int d = nj * 8 + lc * 2 + (r & 1);
                atomicAdd(&g_ctx[((size_t)bh * C_ + c) * C_ + d], ctxa[i][r]);
            }
        }
    }
    if (tid < 96) {
        int head = tid / 48;
        atomicAdd(&g_sum[(batch * H_ + cg * 2 + head) * C_ + tid % 48], ssum);
    }
}

// ================= M precompute: M^T[b][n][h*48+c] = sum_d ctxn[b,h][c][d]*Wproj[h*48+d][n] =================
// grid 64 = (b, h); block 384 threads (one per n). fp32 compute, fp16 out.
__global__ void __launch_bounds__(384)
mcat_kernel(const float* __restrict__ Wproj)
{
    __shared__ float ctxn[C_][C_ + 1];
    __shared__ float sinv[C_];
    const int b = blockIdx.x >> 3;
    const int h = blockIdx.x & 7;
    const int tid = threadIdx.x;
    const int bh = b * H_ + h;

    if (tid < C_) sinv[tid] = 1.0f / g_sum[bh * C_ + tid];
    __syncthreads();
    const float* cb = g_ctx + (size_t)bh * (C_ * C_);
    for (int i = tid; i < C_ * C_; i += 384) {
        int c = i / C_, d = i % C_;
        ctxn[c][d] = cb[i] * sinv[c];
    }
    __syncthreads();

    const int n = tid;   // 0..383
    float acc[C_];
#pragma unroll
    for (int c = 0; c < C_; c++) acc[c] = 0.0f;
#pragma unroll 4
    for (int d = 0; d < C_; d++) {
        float w = Wproj[(size_t)(h * C_ + d) * D_ + n];
#pragma unroll
        for (int c = 0; c < C_; c++) acc[c] += ctxn[c][d] * w;
    }
    __half* ob = g_Mh + ((size_t)b * D_ + n) * D_ + h * C_;
#pragma unroll
    for (int c = 0; c < C_; c += 2)
        *(__half2*)&ob[c] = __floats2half2_rn(acc[c], acc[c + 1]);
}

// ================= fused (eq/s) @ M GEMM: CTA = 64 tokens x N=384, 256 threads =================
#define AQ_ST 392                            // eq row stride in halves (196 words)
#define AP_EQ_B    (64 * AQ_ST * 2)          // 50176
#define AP_W_B     (2 * D_ * PH_ * 2)        // 61440
#define AP_SMEM_BYTES (AP_EQ_B + AP_W_B + 2048)

__global__ void __launch_bounds__(256, 1)
attn_proj_kernel(const float* __restrict__ bias, float* __restrict__ out)
{
    extern __shared__ char smem[];
    __half* eqA  = (__half*)smem;                       // [64][AQ_ST]
    __half* wbuf = (__half*)(smem + AP_EQ_B);           // [2][384][PH_]
    float*  srow = (float*)(smem + AP_EQ_B + AP_W_B);   // [64][8]

    const int tid = threadIdx.x;
    const int wid = tid >> 5;
    const int lane = tid & 31;
    const int lr = lane >> 2;
    const int lc = lane & 3;
    const size_t tok0 = (size_t)blockIdx.x * 64;
    const int batch = blockIdx.x / (SEQ_ / 64);
    const __half* Mb = g_Mh + (size_t)batch * D_ * D_;

    const uint32_t eq_base = smem_u32(eqA);
    const uint32_t w_base = smem_u32(wbuf);

    const int gr = tid >> 2;          // 0..63
    const int gc = (tid & 3) * 8;

    // ---- group 1: eq tile ----
    {
        const __half* eqg = g_eqh + tok0 * D_;
#pragma unroll
        for (int i = 0; i < 12; i++) {
            int col = gc + i * 32;
            cp_async16(eq_base + (gr * AQ_ST + col) * 2, &eqg[(size_t)gr * D_ + col]);
        }
        asm volatile("cp.async.commit_group;");
    }
    // ---- group 2: M chunk 0 ----
    {
#pragma unroll
        for (int i = 0; i < 6; i++) {
            int row = gr + i * 64;
            cp_async16(w_base + (row * PH_ + gc) * 2, &Mb[(size_t)row * D_ + gc]);
        }
        asm volatile("cp.async.commit_group;");
    }
    asm volatile("cp.async.wait_group 1;");
    __syncthreads();

    // ---- rowsums: 512 (token, head) pairs ----
    for (int p = tid; p < 512; p += 256) {
        int r = p >> 3, h = p & 7;
        const uint32_t* rp = (const uint32_t*)(eqA + r * AQ_ST + h * C_);
        float s = 0.0f;
#pragma unroll
        for (int j = 0; j < 24; j++) {
            uint32_t w = rp[j];
            float2 f = __half22float2(*(const __half2*)&w);
            s += f.x + f.y;
        }
        srow[p] = 1.0f / s;
    }
    __syncthreads();

    // ---- scale eq in place: a = eq * (1/s_th), fp16 ----
    for (int p = tid; p < 512; p += 256) {
        int r = p >> 3, h = p & 7;
        const float s = srow[p];
        uint32_t* rp = (uint32_t*)(eqA + r * AQ_ST + h * C_);
#pragma unroll
        for (int j = 0; j < 24; j++) {
            uint32_t w = rp[j];
            float2 f = __half22float2(*(const __half2*)&w);
            __half2 o = __floats2half2_rn(f.x * s, f.y * s);
            rp[j] = *(uint32_t*)&o;
        }
    }
    __syncthreads();

    // ---- mainloop: out[64x384] = a @ M^T ; warp tile 32x96 ----
    const int wm = (wid & 1) * 32;
    const int wn = (wid >> 1) * 96;
    const int lrow = lane & 7;
    const uint32_t a_lane = eq_base + ((wm + lrow + ((lane >> 3) & 1) * 8) * AQ_ST + ((lane >> 4) & 1) * 8) * 2;
    const uint32_t b_lane = ((wn + lrow + ((lane >> 4) & 1) * 8) * PH_ + ((lane >> 3) & 1) * 8) * 2;

    float acc[2][12][4];
#pragma unroll
    for (int i = 0; i < 2; i++)
#pragma unroll
        for (int j = 0; j < 12; j++)
#pragma unroll
            for (int r = 0; r < 4; r++) acc[i][j][r] = 0.0f;

#pragma unroll
    for (int c = 0; c < 12; c++) {
        asm volatile("cp.async.wait_group 0;");
        __syncthreads();

        if (c + 1 < 12) {
            const int k0 = (c + 1) * BK_;
            const uint32_t bb = w_base + ((c + 1) & 1) * D_ * PH_ * 2;
#pragma unroll
            for (int i = 0; i < 6; i++) {
                int row = gr + i * 64;
                cp_async16(bb + (row * PH_ + gc) * 2, &Mb[(size_t)row * D_ + k0 + gc]);
            }
            asm volatile("cp.async.commit_group;");
        }

        const uint32_t abuf = a_lane + c * 64;   // chunk c -> +64 bytes (32 halves)
        const uint32_t bbuf = w_base + (c & 1) * D_ * PH_ * 2 + b_lane;

#pragma unroll
        for (int ks = 0; ks < 2; ks++) {
            uint32_t afr[2][4];
#pragma unroll
            for (int mi = 0; mi < 2; mi++)
                LDMX4(afr[mi][0], afr[mi][1], afr[mi][2], afr[mi][3],
                      abuf + mi * 16 * AQ_ST * 2 + ks * 32);
            uint32_t bfr[12][2];
#pragma unroll
            for (int p = 0; p < 6; p++) {
                uint32_t t0, t1, t2, t3;
                LDMX4(t0, t1, t2, t3, bbuf + p * 16 * PH_ * 2 + ks * 32);
                bfr[2 * p][0] = t0; bfr[2 * p][1] = t1;
                bfr[2 * p + 1][0] = t2; bfr[2 * p + 1][1] = t3;
            }
#pragma unroll
            for (int mi = 0; mi < 2; mi++)
#pragma unroll
                for (int nj = 0; nj < 12; nj++)
                    mma_f16(acc[mi][nj], afr[mi], bfr[nj]);
        }
        __syncthreads();
    }

    // ---- epilogue: fp32 out + bias ----
#pragma unroll
    for (int mi = 0; mi < 2; mi++) {
        const size_t r0 = tok0 + wm + mi * 16 + lr;
#pragma unroll
        for (int nj = 0; nj < 12; nj++) {
            const int col = wn + nj * 8 + lc * 2;
            float2 b2 = *(const float2*)&bias[col];
            float2 v0 = make_float2(acc[mi][nj][0] + b2.x, acc[mi][nj][1] + b2.y);
            float2 v1 = make_float2(acc[mi][nj][2] + b2.x, acc[mi][nj][3] + b2.y);
            *(float2*)&out[r0 * D_ + col] = v0;
            *(float2*)&out[(r0 + 8) * D_ + col] = v1;
        }
    }
}

// ---------------- launch ----------------
extern "C" void kernel_launch(void* const* d_in, const int* in_sizes, int n_in,
                              void* d_out, int out_size)
{
    const float* x     = (const float*)d_in[0];
    const float* Wqkv  = (const float*)d_in[1];
    const float* Wproj = (const float*)d_in[2];
    const float* bproj = (const float*)d_in[3];
    float* out = (float*)d_out;

    __half *p_xh, *p_wtqh;
    cudaGetSymbolAddress((void**)&p_xh, g_xh);
    cudaGetSymbolAddress((void**)&p_wtqh, g_Wtqh);

    cudaFuncSetAttribute(kv_ctx_kernel, cudaFuncAttributeMaxDynamicSharedMemorySize, KV_SMEM_BYTES);
    cudaFuncSetAttribute(attn_proj_kernel, cudaFuncAttributeMaxDynamicSharedMemorySize, AP_SMEM_BYTES);

    // 0) prepass: round x to fp16 (+ zero accumulators); transpose qkv weights
    {
        int n4 = TOK_ * D_ / 4;
        round_f16_kernel<<<(n4 + 255) / 256, 256>>>((const float4*)x, (uint2*)p_xh, n4);
    }
    transpose_f16_kernel<<<dim3(3 * D_ / 32, D_ / 32), dim3(32, 8)>>>(Wqkv, p_wtqh, D_, 3 * D_);

    // 1) fused qkv-GEMM + exp + context accumulation (writes g_eqh, g_ctx, g_sum)
    {
        dim3 grid(4, 256);
        kv_ctx_kernel<<<grid, 256, KV_SMEM_BYTES>>>();
    }

    // 2) fold normalized context into Wproj: M[b] = ctxn[b] @ Wproj (fp32 compute)
    mcat_kernel<<<B_ * H_, 384>>>(Wproj);

    // 3) out = (eq/s) @ M[b] + bias
    attn_proj_kernel<<<TOK_ / 64, 256, AP_SMEM_BYTES>>>(bproj, out);
}

// round 16
// speedup vs baseline: 1.0182x; 1.0171x over previous
#include <cuda_runtime.h>
#include <cuda_fp16.h>
#include <math.h>
#include <stdint.h>

// Problem constants
#define B_      8
#define SEQ_    16384
#define D_      384
#define H_      8
#define C_      48
#define TOK_    (B_ * SEQ_)          // 131072

// ---------------- scratch (static device globals; no allocs allowed) ----------------
__device__ __half g_eqh[(size_t)TOK_ * D_];          // 100 MB : exp(q) fp16
__device__ __half g_xh[(size_t)TOK_ * D_];           // 100 MB : x rounded to fp16
__device__ float  g_ctx[B_ * H_ * C_ * C_];          // unnormalized k^T v context
__device__ float  g_sum[B_ * H_ * C_];               // sum of exp(k) over tokens
__device__ __half g_Mh[(size_t)B_ * D_ * D_];        // fused ctxn@Wproj, [b][n][hc] fp16
__device__ __half g_Wtqh[3 * D_ * D_];               // W_qkv^T, fp16  [1152][384]

__device__ __forceinline__ uint32_t smem_u32(const void* p) {
    uint32_t a;
    asm("{ .reg .u64 t; cvta.to.shared.u64 t, %1; cvt.u32.u64 %0, t; }" : "=r"(a) : "l"(p));
    return a;
}
__device__ __forceinline__ void cp_async16(uint32_t dst, const void* src) {
    asm volatile("cp.async.cg.shared.global [%0], [%1], 16;" :: "r"(dst), "l"(src));
}
__device__ __forceinline__ void mma_f16(float* c, const uint32_t* a, const uint32_t* b) {
    asm volatile(
        "mma.sync.aligned.m16n8k16.row.col.f32.f16.f16.f32 "
        "{%0,%1,%2,%3}, {%4,%5,%6,%7}, {%8,%9}, {%0,%1,%2,%3};"
        : "+f"(c[0]), "+f"(c[1]), "+f"(c[2]), "+f"(c[3])
        : "r"(a[0]), "r"(a[1]), "r"(a[2]), "r"(a[3]), "r"(b[0]), "r"(b[1]));
}
#define LDMX4(r0, r1, r2, r3, addr) \
    asm volatile("ldmatrix.sync.aligned.m8n8.x4.shared.b16 {%0,%1,%2,%3}, [%4];" \
        : "=r"(r0), "=r"(r1), "=r"(r2), "=r"(r3) : "r"(addr))
#define LDMX2(r0, r1, addr) \
    asm volatile("ldmatrix.sync.aligned.m8n8.x2.shared.b16 {%0,%1}, [%2];" \
        : "=r"(r0), "=r"(r1) : "r"(addr))

// ---------------- round x to fp16 (streaming) + zero accumulators ----------------
__global__ void round_f16_kernel(const float4* __restrict__ src, uint2* __restrict__ dst, int n4) {
    int i = blockIdx.x * 256 + threadIdx.x;
    if (i < B_ * H_ * C_ * C_) g_ctx[i] = 0.0f;
    if (i < B_ * H_ * C_)      g_sum[i] = 0.0f;
    if (i < n4) {
        float4 v = src[i];
        __half2 lo = __floats2half2_rn(v.x, v.y);
        __half2 hi = __floats2half2_rn(v.z, v.w);
        uint2 o;
        o.x = *(uint32_t*)&lo;
        o.y = *(uint32_t*)&hi;
        dst[i] = o;
    }
}

// ---------------- weight transpose + fp16 round: src[R][Ccols] -> dst[Ccols][R] ----------------
__global__ void transpose_f16_kernel(const float* __restrict__ src, __half* __restrict__ dst,
                                     int R, int Ccols) {
    __shared__ float t[32][33];
    int bx = blockIdx.x * 32, by = blockIdx.y * 32;
    int tx = threadIdx.x, ty = threadIdx.y;
#pragma unroll
    for (int j = 0; j < 32; j += 8)
        t[ty + j][tx] = src[(size_t)(by + ty + j) * Ccols + bx + tx];
    __syncthreads();
#pragma unroll
    for (int j = 0; j < 32; j += 8)
        dst[(size_t)(bx + ty + j) * R + by + tx] = __float2half_rn(t[tx][ty + j]);
}

#define BM_ 128
#define BK_ 32            // halves per chunk
#define PH_ 40            // halves per smem row slot

// ================= fused qkv-GEMM + ctx kernel (R13 proven config: 256 thr) =================
#define KVN_ 288
#define STH_ 136     // eT/vT row stride in halves (68 words)
#define KV_SMEM_BYTES ((2 * BM_ * PH_ + 2 * KVN_ * PH_) * 2)   // 66560

__global__ void __launch_bounds__(256, 1)
kv_ctx_kernel()
{
    extern __shared__ __half smemh[];
    __half* As = smemh;                          // [2][128][PH_]
    __half* Bs = smemh + 2 * BM_ * PH_;          // [2][288][PH_]
    __half* eT = smemh;                          // [96][STH_]  (epilogue view)
    __half* vT = smemh + 96 * STH_;              // [96][STH_]

    const int tid = threadIdx.x;
    const int wid = tid >> 5;
    const int lane = tid & 31;
    const int cg = blockIdx.x;
    const int ss = blockIdx.y;
    const int lr = lane >> 2;
    const int lc = lane & 3;
    const int wm = (wid & 1) * 64;
    const int wn = (wid >> 1) * 72;   // 4 warps over N=288
    const int gr = tid >> 2;          // 0..63
    const int gc = (tid & 3) * 8;

    const uint32_t as_base = smem_u32(As);
    const uint32_t bs_base = smem_u32(Bs);

    const int lrow = lane & 7;
    const uint32_t a_lane = ((wm + lrow + ((lane >> 3) & 1) * 8) * PH_ + ((lane >> 4) & 1) * 8) * 2;
    const uint32_t b_lane = ((wn + lrow + ((lane >> 4) & 1) * 8) * PH_ + ((lane >> 3) & 1) * 8) * 2;

    const __half* Wq = g_Wtqh + (size_t)(cg * 96) * D_;
    const __half* Wk = g_Wtqh + (size_t)(D_ + cg * 96) * D_;
    const __half* Wv = g_Wtqh + (size_t)(2 * D_ + cg * 96) * D_;

    const int batch = ss / 32;

    float ctxa[5][4];
#pragma unroll
    for (int i = 0; i < 5; i++)
#pragma unroll
        for (int r = 0; r < 4; r++) ctxa[i][r] = 0.0f;
    float ssum = 0.0f;

    for (int rb = 0; rb < 4; rb++) {
        const size_t tok0 = ((size_t)ss * 4 + rb) * 128;
        const __half* A = g_xh + tok0 * D_;

        float acc[4][9][4];
#pragma unroll
        for (int i = 0; i < 4; i++)
#pragma unroll
            for (int j = 0; j < 9; j++)
#pragma unroll
                for (int r = 0; r < 4; r++) acc[i][j][r] = 0.0f;

        {
#pragma unroll
            for (int i = 0; i < 2; i++) {
                int row = gr + i * 64;
                cp_async16(as_base + (row * PH_ + gc) * 2, &A[(size_t)row * D_ + gc]);
            }
#pragma unroll
            for (int i = 0; i < 5; i++) {
                int row = gr + i * 64;
                if (row < KVN_) {
                    const __half* src = (row < 96) ? &Wq[(size_t)row * D_ + gc]
                                     : (row < 192) ? &Wk[(size_t)(row - 96) * D_ + gc]
                                                   : &Wv[(size_t)(row - 192) * D_ + gc];
                    cp_async16(bs_base + (row * PH_ + gc) * 2, src);
                }
            }
            asm volatile("cp.async.commit_group;");
        }

#pragma unroll
        for (int c = 0; c < D_ / BK_; c++) {
            asm volatile("cp.async.wait_group 0;");
            __syncthreads();

            if (c + 1 < D_ / BK_) {
                const int k0 = (c + 1) * BK_;
                const int buf = (c + 1) & 1;
                const uint32_t ab = as_base + buf * BM_ * PH_ * 2;
                const uint32_t bb = bs_base + buf * KVN_ * PH_ * 2;
#pragma unroll
                for (int i = 0; i < 2; i++) {
                    int row = gr + i * 64;
                    cp_async16(ab + (row * PH_ + gc) * 2, &A[(size_t)row * D_ + k0 + gc]);
                }
#pragma unroll
                for (int i = 0; i < 5; i++) {
                    int row = gr + i * 64;
                    if (row < KVN_) {
                        const __half* src = (row < 96) ? &Wq[(size_t)row * D_ + k0 + gc]
                                         : (row < 192) ? &Wk[(size_t)(row - 96) * D_ + k0 + gc]
                                                       : &Wv[(size_t)(row - 192) * D_ + k0 + gc];
                        cp_async16(bb + (row * PH_ + gc) * 2, src);
                    }
                }
                asm volatile("cp.async.commit_group;");
            }

            const uint32_t abuf = as_base + (c & 1) * BM_ * PH_ * 2 + a_lane;
            const uint32_t bbuf = bs_base + (c & 1) * KVN_ * PH_ * 2 + b_lane;

#pragma unroll
            for (int ks = 0; ks < 2; ks++) {
                uint32_t afr[4][4];
#pragma unroll
                for (int mi = 0; mi < 4; mi++)
                    LDMX4(afr[mi][0], afr[mi][1], afr[mi][2], afr[mi][3],
                          abuf + mi * 16 * PH_ * 2 + ks * 32);
                uint32_t bfr[9][2];
#pragma unroll
                for (int p = 0; p < 4; p++) {
                    uint32_t t0, t1, t2, t3;
                    LDMX4(t0, t1, t2, t3, bbuf + p * 16 * PH_ * 2 + ks * 32);
                    bfr[2 * p][0] = t0; bfr[2 * p][1] = t1;
                    bfr[2 * p + 1][0] = t2; bfr[2 * p + 1][1] = t3;
                }
                LDMX2(bfr[8][0], bfr[8][1], bbuf + 4 * 16 * PH_ * 2 + ks * 32);
#pragma unroll
                for (int mi = 0; mi < 4; mi++)
#pragma unroll
                    for (int nj = 0; nj < 9; nj++)
                        mma_f16(acc[mi][nj], afr[mi], bfr[nj]);
            }
            __syncthreads();
        }

        // ---- epilogue: q -> exp -> gmem fp16 ; k -> exp -> eT ; v -> vT ----
        {
            __half* eqb = g_eqh + tok0 * D_ + cg * 96;
#pragma unroll
            for (int nj = 0; nj < 9; nj++) {
                const int chbase = wn + nj * 8;
                if (chbase < 96) {
                    const int ch = chbase + lc * 2;
#pragma unroll
                    for (int mi = 0; mi < 4; mi++) {
                        int tl = wm + mi * 16 + lr;
                        __half2 v0 = __floats2half2_rn(__expf(acc[mi][nj][0]), __expf(acc[mi][nj][1]));
                        __half2 v1 = __floats2half2_rn(__expf(acc[mi][nj][2]), __expf(acc[mi][nj][3]));
                        *(__half2*)&eqb[(size_t)tl * D_ + ch] = v0;
                        *(__half2*)&eqb[(size_t)(tl + 8) * D_ + ch] = v1;
                    }
                } else if (chbase < 192) {
#pragma unroll
                    for (int mi = 0; mi < 4; mi++) {
#pragma unroll
                        for (int r = 0; r < 4; r++) {
                            int ch = chbase - 96 + lc * 2 + (r & 1);
                            int tl = wm + mi * 16 + lr + ((r >> 1) ? 8 : 0);
                            eT[ch * STH_ + tl] = __float2half_rn(__expf(acc[mi][nj][r]));
                        }
                    }
                } else {
#pragma unroll
                    for (int mi = 0; mi < 4; mi++) {
#pragma unroll
                        for (int r = 0; r < 4; r++) {
                            int ch = chbase - 192 + lc * 2 + (r & 1);
                            int tl = wm + mi * 16 + lr + ((r >> 1) ? 8 : 0);
                            vT[ch * STH_ + tl] = __float2half_rn(acc[mi][nj][r]);
                        }
                    }
                }
            }
        }
        __syncthreads();

        // ---- ctx += e^T v via fp16 MMA: 36 m16n8 tiles, k=128 (8 k16-steps) ----
        const uint32_t* eTw = (const uint32_t*)eT;
        const uint32_t* vTw = (const uint32_t*)vT;
#pragma unroll
        for (int i = 0; i < 5; i++) {
            int t = wid + 8 * i;
            if (t < 36) {
                int head = t / 18, rem = t % 18;
                int mi = rem / 6, nj = rem % 6;
                const int ar = head * 48 + mi * 16;
                const int br = head * 48 + nj * 8;
#pragma unroll
                for (int ks = 0; ks < 8; ks++) {
                    const int kw = ks * 8 + lc;
                    uint32_t a[4], b[2];
                    a[0] = eTw[(ar + lr) * 68 + kw];
                    a[1] = eTw[(ar + lr + 8) * 68 + kw];
                    a[2] = eTw[(ar + lr) * 68 + kw + 4];
                    a[3] = eTw[(ar + lr + 8) * 68 + kw + 4];
                    b[0] = vTw[(br + lr) * 68 + kw];
                    b[1] = vTw[(br + lr) * 68 + kw + 4];
                    mma_f16(ctxa[i], a, b);
                }
            }
        }

        // ---- per-channel exp-sum ----
        if (tid < 96) {
            const uint32_t* row = (const uint32_t*)(eT + tid * STH_);
            float s = 0.0f;
#pragma unroll
            for (int j = 0; j < 64; j++) {
                uint32_t w = row[j];
                float2 f = __half22float2(*(const __half2*)&w);
                s += f.x + f.y;
            }
            ssum += s;
        }
        __syncthreads();
    }

    // ---- atomics ----
#pragma unroll
    for (int i = 0; i < 5; i++) {
        int t = wid + 8 * i;
        if (t < 36) {
            int head = t / 18, rem = t % 18;
            int mi = rem / 6, nj = rem % 6;
            int bh = (batch * H_ + cg * 2 + head);
#pragma unroll
            for (int r = 0; r < 4; r++) {
                int c = mi * 16 + lr + ((r >> 1) ? 8 : 0);
                int d = nj * 8 + lc * 2 + (r & 1);
                atomicAdd(&g_ctx[((size_t)bh * C_ + c) * C_ + d], ctxa[i][r]);
            }
        }
    }
    if (tid < 96) {
        int head = tid / 48;
        atomicAdd(&g_sum[(batch * H_ + cg * 2 + head) * C_ + tid % 48], ssum);
    }
}

// ================= M precompute v2: grid (64 bh, 6 nc), 64 threads =================
// M^T[b][n][h*48+c] = sum_d ctxn[b,h][c][d] * Wproj[h*48+d][n]; fp32 compute, fp16 out.
__global__ void __launch_bounds__(64)
mcat_kernel(const float* __restrict__ Wproj)
{
    __shared__ float ctxn[C_][C_ + 1];
    __shared__ float sinv[C_];
    const int bh = blockIdx.x;
    const int b = bh >> 3;
    const int h = bh & 7;
    const int tid = threadIdx.x;

    if (tid < C_) sinv[tid] = 1.0f / g_sum[bh * C_ + tid];
    __syncthreads();
    const float* cb = g_ctx + (size_t)bh * (C_ * C_);
    for (int i = tid; i < C_ * C_; i += 64) {
        int c = i / C_, d = i % C_;
        ctxn[c][d] = cb[i] * sinv[c];
    }
    __syncthreads();

    const int n = blockIdx.y * 64 + tid;   // 0..383
    float acc[C_];
#pragma unroll
    for (int c = 0; c < C_; c++) acc[c] = 0.0f;
#pragma unroll 4
    for (int d = 0; d < C_; d++) {
        float w = Wproj[(size_t)(h * C_ + d) * D_ + n];
#pragma unroll
        for (int c = 0; c < C_; c++) acc[c] += ctxn[c][d] * w;
    }
    __half* ob = g_Mh + ((size_t)b * D_ + n) * D_ + h * C_;
#pragma unroll
    for (int c = 0; c < C_; c += 2)
        *(__half2*)&ob[c] = __floats2half2_rn(acc[c], acc[c + 1]);
}

// ================= fused (eq/s) @ M GEMM: CTA = 64 tokens x N=384, 256 threads =================
#define AQ_ST 392                            // eq row stride in halves (196 words)
#define AP_EQ_B    (64 * AQ_ST * 2)          // 50176
#define AP_W_B     (2 * D_ * PH_ * 2)        // 61440
#define AP_SMEM_BYTES (AP_EQ_B + AP_W_B + 256)

__global__ void __launch_bounds__(256, 1)
attn_proj_kernel(const float* __restrict__ bias, float* __restrict__ out)
{
    extern __shared__ char smem[];
    __half* eqA  = (__half*)smem;                       // [64][AQ_ST]
    __half* wbuf = (__half*)(smem + AP_EQ_B);           // [2][384][PH_]

    const int tid = threadIdx.x;
    const int wid = tid >> 5;
    const int lane = tid & 31;
    const int lr = lane >> 2;
    const int lc = lane & 3;
    const size_t tok0 = (size_t)blockIdx.x * 64;
    const int batch = blockIdx.x / (SEQ_ / 64);
    const __half* Mb = g_Mh + (size_t)batch * D_ * D_;

    const uint32_t eq_base = smem_u32(eqA);
    const uint32_t w_base = smem_u32(wbuf);

    const int gr = tid >> 2;          // 0..63
    const int gc = (tid & 3) * 8;

    // ---- group 1: eq tile ----
    {
        const __half* eqg = g_eqh + tok0 * D_;
#pragma unroll
        for (int i = 0; i < 12; i++) {
            int col = gc + i * 32;
            cp_async16(eq_base + (gr * AQ_ST + col) * 2, &eqg[(size_t)gr * D_ + col]);
        }
        asm volatile("cp.async.commit_group;");
    }
    // ---- group 2: M chunk 0 ----
    {
#pragma unroll
        for (int i = 0; i < 6; i++) {
            int row = gr + i * 64;
            cp_async16(w_base + (row * PH_ + gc) * 2, &Mb[(size_t)row * D_ + gc]);
        }
        asm volatile("cp.async.commit_group;");
    }
    asm volatile("cp.async.wait_group 1;");
    __syncthreads();

    // ---- fused rowsum + in-place scale: a = eq * (1/s_th), register-resident ----
    for (int p = tid; p < 512; p += 256) {
        int r = p >> 3, hh = p & 7;
        uint32_t* rp = (uint32_t*)(eqA + r * AQ_ST + hh * C_);
        uint32_t w[24];
        float s = 0.0f;
#pragma unroll
        for (int j = 0; j < 24; j++) {
            w[j] = rp[j];
            float2 f = __half22float2(*(const __half2*)&w[j]);
            s += f.x + f.y;
        }
        s = 1.0f / s;
#pragma unroll
        for (int j = 0; j < 24; j++) {
            float2 f = __half22float2(*(const __half2*)&w[j]);
            __half2 o = __floats2half2_rn(f.x * s, f.y * s);
            rp[j] = *(uint32_t*)&o;
        }
    }
    __syncthreads();

    // ---- mainloop: out[64x384] = a @ M^T ; warp tile 32x96 ----
    const int wm = (wid & 1) * 32;
    const int wn = (wid >> 1) * 96;
    const int lrow = lane & 7;
    const uint32_t a_lane = eq_base + ((wm + lrow + ((lane >> 3) & 1) * 8) * AQ_ST + ((lane >> 4) & 1) * 8) * 2;
    const uint32_t b_lane = ((wn + lrow + ((lane >> 4) & 1) * 8) * PH_ + ((lane >> 3) & 1) * 8) * 2;

    float acc[2][12][4];
#pragma unroll
    for (int i = 0; i < 2; i++)
#pragma unroll
        for (int j = 0; j < 12; j++)
#pragma unroll
            for (int r = 0; r < 4; r++) acc[i][j][r] = 0.0f;

#pragma unroll
    for (int c = 0; c < 12; c++) {
        asm volatile("cp.async.wait_group 0;");
        __syncthreads();

        if (c + 1 < 12) {
            const int k0 = (c + 1) * BK_;
            const uint32_t bb = w_base + ((c + 1) & 1) * D_ * PH_ * 2;
#pragma unroll
            for (int i = 0; i < 6; i++) {
                int row = gr + i * 64;
                cp_async16(bb + (row * PH_ + gc) * 2, &Mb[(size_t)row * D_ + k0 + gc]);
            }
            asm volatile("cp.async.commit_group;");
        }

        const uint32_t abuf = a_lane + c * 64;   // chunk c -> +64 bytes (32 halves)
        const uint32_t bbuf = w_base + (c & 1) * D_ * PH_ * 2 + b_lane;

#pragma unroll
        for (int ks = 0; ks < 2; ks++) {
            uint32_t afr[2][4];
#pragma unroll
            for (int mi = 0; mi < 2; mi++)
                LDMX4(afr[mi][0], afr[mi][1], afr[mi][2], afr[mi][3],
                      abuf + mi * 16 * AQ_ST * 2 + ks * 32);
            uint32_t bfr[12][2];
#pragma unroll
            for (int p = 0; p < 6; p++) {
                uint32_t t0, t1, t2, t3;
                LDMX4(t0, t1, t2, t3, bbuf + p * 16 * PH_ * 2 + ks * 32);
                bfr[2 * p][0] = t0; bfr[2 * p][1] = t1;
                bfr[2 * p + 1][0] = t2; bfr[2 * p + 1][1] = t3;
            }
#pragma unroll
            for (int mi = 0; mi < 2; mi++)
#pragma unroll
                for (int nj = 0; nj < 12; nj++)
                    mma_f16(acc[mi][nj], afr[mi], bfr[nj]);
        }
        __syncthreads();
    }

    // ---- epilogue: fp32 out + bias ----
#pragma unroll
    for (int mi = 0; mi < 2; mi++) {
        const size_t r0 = tok0 + wm + mi * 16 + lr;
#pragma unroll
        for (int nj = 0; nj < 12; nj++) {
            const int col = wn + nj * 8 + lc * 2;
            float2 b2 = *(const float2*)&bias[col];
            float2 v0 = make_float2(acc[mi][nj][0] + b2.x, acc[mi][nj][1] + b2.y);
            float2 v1 = make_float2(acc[mi][nj][2] + b2.x, acc[mi][nj][3] + b2.y);
            *(float2*)&out[r0 * D_ + col] = v0;
            *(float2*)&out[(r0 + 8) * D_ + col] = v1;
        }
    }
}

// ---------------- launch ----------------
extern "C" void kernel_launch(void* const* d_in, const int* in_sizes, int n_in,
                              void* d_out, int out_size)
{
    const float* x     = (const float*)d_in[0];
    const float* Wqkv  = (const float*)d_in[1];
    const float* Wproj = (const float*)d_in[2];
    const float* bproj = (const float*)d_in[3];
    float* out = (float*)d_out;

    __half *p_xh, *p_wtqh;
    cudaGetSymbolAddress((void**)&p_xh, g_xh);
    cudaGetSymbolAddress((void**)&p_wtqh, g_Wtqh);

    cudaFuncSetAttribute(kv_ctx_kernel, cudaFuncAttributeMaxDynamicSharedMemorySize, KV_SMEM_BYTES);
    cudaFuncSetAttribute(attn_proj_kernel, cudaFuncAttributeMaxDynamicSharedMemorySize, AP_SMEM_BYTES);

    // 0) prepass: round x to fp16 (+ zero accumulators); transpose qkv weights
    {
        int n4 = TOK_ * D_ / 4;
        round_f16_kernel<<<(n4 + 255) / 256, 256>>>((const float4*)x, (uint2*)p_xh, n4);
    }
    transpose_f16_kernel<<<dim3(3 * D_ / 32, D_ / 32), dim3(32, 8)>>>(Wqkv, p_wtqh, D_, 3 * D_);

    // 1) fused qkv-GEMM + exp + context accumulation (writes g_eqh, g_ctx, g_sum)
    {
        dim3 grid(4, 256);
        kv_ctx_kernel<<<grid, 256, KV_SMEM_BYTES>>>();
    }

    // 2) fold normalized context into Wproj: M[b] = ctxn[b] @ Wproj (fp32 compute)
    mcat_kernel<<<dim3(B_ * H_, 6), 64>>>(Wproj);

    // 3) out = (eq/s) @ M[b] + bias
    attn_proj_kernel<<<TOK_ / 64, 256, AP_SMEM_BYTES>>>(bproj, out);
}